// round 1
// baseline (speedup 1.0000x reference)
#include <cuda_runtime.h>
#include <math.h>

// Problem shape (fixed by the dataset): B=512 batches, L=512 tokens, D=256 dims.
#define BATCH 512
#define L 512
#define DDIM 256
#define EPSV 1e-6f

// Per-row scratch: r1[b,i] = sum(a^2) + 2*eps*sum(a)
//                  r2[b,j] = sum((y-eps)^2) = sum(y^2) - 2*eps*sum(y) + D*eps^2
// Then d2[i,j] = r1[i] + r2[j] - 2 * dot(A_i, Y_j_raw)   (exact eps folding)
__device__ float g_r1[BATCH * L];
__device__ float g_r2[BATCH * L];

// ---------------------------------------------------------------------------
// Kernel 1: row norms. One warp per row; each lane reads 2 float4 (8 floats).
// ---------------------------------------------------------------------------
__global__ void norms_kernel(const float* __restrict__ A,
                             const float* __restrict__ B2) {
    int warp = (blockIdx.x * blockDim.x + threadIdx.x) >> 5;
    int lane = threadIdx.x & 31;
    if (warp >= BATCH * L) return;

    const float4* a4 = reinterpret_cast<const float4*>(A + (size_t)warp * DDIM);
    const float4* b4 = reinterpret_cast<const float4*>(B2 + (size_t)warp * DDIM);

    float sa = 0.f, ssa = 0.f, sb = 0.f, ssb = 0.f;
#pragma unroll
    for (int i = 0; i < 2; i++) {
        float4 va = a4[lane + 32 * i];
        float4 vb = b4[lane + 32 * i];
        sa  += va.x + va.y + va.z + va.w;
        ssa += va.x * va.x + va.y * va.y + va.z * va.z + va.w * va.w;
        sb  += vb.x + vb.y + vb.z + vb.w;
        ssb += vb.x * vb.x + vb.y * vb.y + vb.z * vb.z + vb.w * vb.w;
    }
#pragma unroll
    for (int off = 16; off > 0; off >>= 1) {
        sa  += __shfl_xor_sync(0xffffffffu, sa,  off);
        ssa += __shfl_xor_sync(0xffffffffu, ssa, off);
        sb  += __shfl_xor_sync(0xffffffffu, sb,  off);
        ssb += __shfl_xor_sync(0xffffffffu, ssb, off);
    }
    if (lane == 0) {
        g_r1[warp] = ssa + 2.0f * EPSV * sa;
        g_r2[warp] = ssb - 2.0f * EPSV * sb + (float)DDIM * EPSV * EPSV;
    }
}

// ---------------------------------------------------------------------------
// Kernel 2: per-batch 128x128x(K=256) "GEMM" with distance epilogue.
// Classic SGEMM: BM=BN=128, BK=8, TM=TN=8, 256 threads, double-buffered smem.
// Both operands are K-contiguous (A * B^T pattern) -> identical load paths.
// ---------------------------------------------------------------------------
#define BM 128
#define BN 128
#define BK 8

__global__ __launch_bounds__(256)
void dist_kernel(const float* __restrict__ A,
                 const float* __restrict__ B2,
                 float* __restrict__ out) {
    __shared__ float As[2][BK][BM];
    __shared__ float Bs[2][BK][BN];

    const int b  = blockIdx.z;
    const int m0 = blockIdx.y * BM;
    const int n0 = blockIdx.x * BN;

    const float* Ab = A  + ((size_t)b * L + m0) * DDIM;
    const float* Bb = B2 + ((size_t)b * L + n0) * DDIM;

    const int tid  = threadIdx.x;
    const int lrow = tid >> 1;          // 0..127 : tile row loaded by this thread
    const int lc4  = (tid & 1) * 4;     // 0 or 4 : float4 column offset within BK

    const int tx = tid & 15;            // 0..15
    const int ty = tid >> 4;            // 0..15

    float acc[8][8];
#pragma unroll
    for (int i = 0; i < 8; i++)
#pragma unroll
        for (int j = 0; j < 8; j++) acc[i][j] = 0.f;

    // prefetch k-block 0 into buffer 0
    float4 pa = *reinterpret_cast<const float4*>(Ab + (size_t)lrow * DDIM + lc4);
    float4 pb = *reinterpret_cast<const float4*>(Bb + (size_t)lrow * DDIM + lc4);
    As[0][lc4 + 0][lrow] = pa.x;  As[0][lc4 + 1][lrow] = pa.y;
    As[0][lc4 + 2][lrow] = pa.z;  As[0][lc4 + 3][lrow] = pa.w;
    Bs[0][lc4 + 0][lrow] = pb.x;  Bs[0][lc4 + 1][lrow] = pb.y;
    Bs[0][lc4 + 2][lrow] = pb.z;  Bs[0][lc4 + 3][lrow] = pb.w;
    __syncthreads();

    int buf = 0;
    const int NKT = DDIM / BK;          // 32 k-tiles
#pragma unroll 1
    for (int kt = 0; kt < NKT; kt++) {
        if (kt + 1 < NKT) {
            int koff = (kt + 1) * BK + lc4;
            pa = *reinterpret_cast<const float4*>(Ab + (size_t)lrow * DDIM + koff);
            pb = *reinterpret_cast<const float4*>(Bb + (size_t)lrow * DDIM + koff);
        }
#pragma unroll
        for (int k = 0; k < BK; k++) {
            float4 a0 = *reinterpret_cast<const float4*>(&As[buf][k][ty * 4]);
            float4 a1 = *reinterpret_cast<const float4*>(&As[buf][k][64 + ty * 4]);
            float4 b0 = *reinterpret_cast<const float4*>(&Bs[buf][k][tx * 4]);
            float4 b1 = *reinterpret_cast<const float4*>(&Bs[buf][k][64 + tx * 4]);
            float am[8] = {a0.x, a0.y, a0.z, a0.w, a1.x, a1.y, a1.z, a1.w};
            float bn[8] = {b0.x, b0.y, b0.z, b0.w, b1.x, b1.y, b1.z, b1.w};
#pragma unroll
            for (int i = 0; i < 8; i++)
#pragma unroll
                for (int j = 0; j < 8; j++)
                    acc[i][j] = fmaf(am[i], bn[j], acc[i][j]);
        }
        if (kt + 1 < NKT) {
            int nb = buf ^ 1;
            As[nb][lc4 + 0][lrow] = pa.x;  As[nb][lc4 + 1][lrow] = pa.y;
            As[nb][lc4 + 2][lrow] = pa.z;  As[nb][lc4 + 3][lrow] = pa.w;
            Bs[nb][lc4 + 0][lrow] = pb.x;  Bs[nb][lc4 + 1][lrow] = pb.y;
            Bs[nb][lc4 + 2][lrow] = pb.z;  Bs[nb][lc4 + 3][lrow] = pb.w;
            __syncthreads();
            buf = nb;
        }
    }

    // Epilogue: d = sqrt(max(r1 + r2 - 2*dot, 0)), vectorized float4 stores.
    const int gm0 = m0 + ty * 4;
    const int gm1 = m0 + 64 + ty * 4;
    const int gn0 = n0 + tx * 4;
    const int gn1 = n0 + 64 + tx * 4;

    float r1v[8], r2v[8];
#pragma unroll
    for (int i = 0; i < 4; i++) {
        r1v[i]     = g_r1[b * L + gm0 + i];
        r1v[4 + i] = g_r1[b * L + gm1 + i];
        r2v[i]     = g_r2[b * L + gn0 + i];
        r2v[4 + i] = g_r2[b * L + gn1 + i];
    }

#pragma unroll
    for (int i = 0; i < 8; i++) {
        int row = (i < 4) ? (gm0 + i) : (gm1 + i - 4);
        float* O = out + (size_t)b * L * L + (size_t)row * L;
        float4 v0, v1;
        v0.x = sqrtf(fmaxf(r1v[i] + r2v[0] - 2.f * acc[i][0], 0.f));
        v0.y = sqrtf(fmaxf(r1v[i] + r2v[1] - 2.f * acc[i][1], 0.f));
        v0.z = sqrtf(fmaxf(r1v[i] + r2v[2] - 2.f * acc[i][2], 0.f));
        v0.w = sqrtf(fmaxf(r1v[i] + r2v[3] - 2.f * acc[i][3], 0.f));
        v1.x = sqrtf(fmaxf(r1v[i] + r2v[4] - 2.f * acc[i][4], 0.f));
        v1.y = sqrtf(fmaxf(r1v[i] + r2v[5] - 2.f * acc[i][5], 0.f));
        v1.z = sqrtf(fmaxf(r1v[i] + r2v[6] - 2.f * acc[i][6], 0.f));
        v1.w = sqrtf(fmaxf(r1v[i] + r2v[7] - 2.f * acc[i][7], 0.f));
        *reinterpret_cast<float4*>(O + gn0) = v0;
        *reinterpret_cast<float4*>(O + gn1) = v1;
    }
}

// ---------------------------------------------------------------------------
extern "C" void kernel_launch(void* const* d_in, const int* in_sizes, int n_in,
                              void* d_out, int out_size) {
    const float* A  = (const float*)d_in[0];   // states_1 [512,512,256] f32
    const float* B2 = (const float*)d_in[1];   // states_2 [512,512,256] f32
    float* out = (float*)d_out;                // [512,512,512] f32

    (void)in_sizes; (void)n_in; (void)out_size;

    // 1) row norms: one warp per row, 8 warps per block
    {
        int rows = BATCH * L;
        int warps_per_blk = 8;
        int blocks = rows / warps_per_blk;
        norms_kernel<<<blocks, warps_per_blk * 32>>>(A, B2);
    }

    // 2) distance GEMM: grid (n-tiles, m-tiles, batch)
    {
        dim3 grid(L / BN, L / BM, BATCH);
        dist_kernel<<<grid, 256>>>(A, B2, out);
    }
}

// round 3
// speedup vs baseline: 1.4457x; 1.4457x over previous
#include <cuda_runtime.h>
#include <math.h>
#include <stdint.h>

// Problem shape (fixed): B=512, L=512, D=256, fp32.
#define BATCH 512
#define LDIM  512
#define DDIM  256
#define EPSV  1e-6f

#define TM 128
#define TN 128
#define KCH 32               // K elements staged per chunk
#define NCHUNK (DDIM/KCH)    // 8
#define RS 40                // smem row stride in floats (bank-conflict-free)

// smem (floats): As[2][128][RS] | Bs[2][128][RS] | r1[128] | r2[128]
#define TILEF   (128*RS)           // 5120 floats
#define AS_OFF(b) ((b)*TILEF)
#define BS_OFF(b) (2*TILEF + (b)*TILEF)
#define R1_OFF   (4*TILEF)
#define R2_OFF   (4*TILEF + 128)
#define SMEM_FLOATS (4*TILEF + 256)
#define SMEM_BYTES  (SMEM_FLOATS*4)   // 82,944 B

__device__ __forceinline__ uint32_t f2tf32(float x) {
    uint32_t r; asm("cvt.rna.tf32.f32 %0, %1;" : "=r"(r) : "f"(x)); return r;
}
__device__ __forceinline__ float fsqrt_fast(float x) {
    float y; asm("sqrt.approx.f32 %0, %1;" : "=f"(y) : "f"(x)); return y;
}
__device__ __forceinline__ void mma_tf32(float* c,
                                         uint32_t a0, uint32_t a1, uint32_t a2, uint32_t a3,
                                         uint32_t b0, uint32_t b1) {
    asm volatile(
        "mma.sync.aligned.m16n8k8.row.col.f32.tf32.tf32.f32 "
        "{%0,%1,%2,%3}, {%4,%5,%6,%7}, {%8,%9}, {%0,%1,%2,%3};"
        : "+f"(c[0]), "+f"(c[1]), "+f"(c[2]), "+f"(c[3])
        : "r"(a0), "r"(a1), "r"(a2), "r"(a3), "r"(b0), "r"(b1));
}

// ---------------------------------------------------------------------------
__global__ __launch_bounds__(256, 1)
void dist_tf32_kernel(const float* __restrict__ A, const float* __restrict__ B,
                      float* __restrict__ out) {
    extern __shared__ float smf[];

    const int tid = threadIdx.x;
    const int wid = tid >> 5, lid = tid & 31;
    const int b  = blockIdx.z;
    const int m0 = blockIdx.y * TM;
    const int n0 = blockIdx.x * TN;

    // ---- loader mapping: 2 threads per row ----
    const int row = tid >> 1;        // 0..127
    const int h   = tid & 1;         // column half (16 floats each)
    const float* Ap = A + ((size_t)(b * LDIM + m0 + row)) * DDIM;
    const float* Bp = B + ((size_t)(b * LDIM + n0 + row)) * DDIM;

    // ---- compute mapping: 2x4 warp grid, 64x32 warp tiles ----
    const int wm = wid >> 2;         // 0..1
    const int wn = wid & 3;          // 0..3
    const int g   = lid >> 2;        // 0..7
    const int tig = lid & 3;         // 0..3

    float acc[4][4][4];
#pragma unroll
    for (int mt = 0; mt < 4; mt++)
#pragma unroll
        for (int nt = 0; nt < 4; nt++)
#pragma unroll
            for (int r = 0; r < 4; r++) acc[mt][nt][r] = 0.f;

    float ssa = 0.f, sa = 0.f, ssb = 0.f, sB = 0.f;
    float4 av[4], bv[4];

    // ---- prologue: load + stage chunk 0 ----
#pragma unroll
    for (int j = 0; j < 4; j++) {
        av[j] = *reinterpret_cast<const float4*>(Ap + h * 16 + 4 * j);
        bv[j] = *reinterpret_cast<const float4*>(Bp + h * 16 + 4 * j);
    }
    {
        const int jrot = row & 3;
#pragma unroll
        for (int t = 0; t < 4; t++) {
            int j = (t + jrot) & 3;
            float4 a = av[j], v = bv[j];
            ssa = fmaf(a.x, a.x, ssa); ssa = fmaf(a.y, a.y, ssa);
            ssa = fmaf(a.z, a.z, ssa); ssa = fmaf(a.w, a.w, ssa);
            sa += a.x + a.y + a.z + a.w;
            ssb = fmaf(v.x, v.x, ssb); ssb = fmaf(v.y, v.y, ssb);
            ssb = fmaf(v.z, v.z, ssb); ssb = fmaf(v.w, v.w, ssb);
            sB += v.x + v.y + v.z + v.w;
            uint4 ua = make_uint4(f2tf32(a.x), f2tf32(a.y), f2tf32(a.z), f2tf32(a.w));
            uint4 ub = make_uint4(f2tf32(v.x), f2tf32(v.y), f2tf32(v.z), f2tf32(v.w));
            int col = h * 16 + 4 * j;
            *reinterpret_cast<uint4*>(&smf[AS_OFF(0) + row * RS + col]) = ua;
            *reinterpret_cast<uint4*>(&smf[BS_OFF(0) + row * RS + col]) = ub;
        }
    }
    __syncthreads();

    const int arow0 = wm * 64 + g;
    const int brow0 = wn * 32 + g;
    const int klane = 2 * tig;

#pragma unroll 1
    for (int kt = 0; kt < NCHUNK; kt++) {
        const int buf = kt & 1;

        if (kt + 1 < NCHUNK) {
            const int cb = (kt + 1) * KCH + h * 16;
#pragma unroll
            for (int j = 0; j < 4; j++) {
                av[j] = *reinterpret_cast<const float4*>(Ap + cb + 4 * j);
                bv[j] = *reinterpret_cast<const float4*>(Bp + cb + 4 * j);
            }
        }

        // ---- MMA over this chunk: 4 k8-steps ----
        const float* As = &smf[AS_OFF(buf)];
        const float* Bs = &smf[BS_OFF(buf)];
#pragma unroll
        for (int s = 0; s < 4; s++) {
            const int ko = 8 * s + klane;
            uint2 afr[4][2], bfr[4];
#pragma unroll
            for (int mt = 0; mt < 4; mt++) {
                afr[mt][0] = *reinterpret_cast<const uint2*>(&As[(arow0 + mt * 16) * RS + ko]);
                afr[mt][1] = *reinterpret_cast<const uint2*>(&As[(arow0 + mt * 16 + 8) * RS + ko]);
            }
#pragma unroll
            for (int nt = 0; nt < 4; nt++)
                bfr[nt] = *reinterpret_cast<const uint2*>(&Bs[(brow0 + nt * 8) * RS + ko]);
#pragma unroll
            for (int mt = 0; mt < 4; mt++)
#pragma unroll
                for (int nt = 0; nt < 4; nt++)
                    mma_tf32(acc[mt][nt],
                             afr[mt][0].x, afr[mt][1].x, afr[mt][0].y, afr[mt][1].y,
                             bfr[nt].x, bfr[nt].y);
        }

        if (kt + 1 < NCHUNK) {
            const int nb = buf ^ 1;
            const int jrot = row & 3;
#pragma unroll
            for (int t = 0; t < 4; t++) {
                int j = (t + jrot) & 3;
                float4 a = av[j], v = bv[j];
                ssa = fmaf(a.x, a.x, ssa); ssa = fmaf(a.y, a.y, ssa);
                ssa = fmaf(a.z, a.z, ssa); ssa = fmaf(a.w, a.w, ssa);
                sa += a.x + a.y + a.z + a.w;
                ssb = fmaf(v.x, v.x, ssb); ssb = fmaf(v.y, v.y, ssb);
                ssb = fmaf(v.z, v.z, ssb); ssb = fmaf(v.w, v.w, ssb);
                sB += v.x + v.y + v.z + v.w;
                uint4 ua = make_uint4(f2tf32(a.x), f2tf32(a.y), f2tf32(a.z), f2tf32(a.w));
                uint4 ub = make_uint4(f2tf32(v.x), f2tf32(v.y), f2tf32(v.z), f2tf32(v.w));
                int col = h * 16 + 4 * j;
                *reinterpret_cast<uint4*>(&smf[AS_OFF(nb) + row * RS + col]) = ua;
                *reinterpret_cast<uint4*>(&smf[BS_OFF(nb) + row * RS + col]) = ub;
            }
            __syncthreads();
        }
    }

    // ---- norms: combine thread pair (tid, tid^1), publish to smem ----
    ssa += __shfl_xor_sync(0xffffffffu, ssa, 1);
    sa  += __shfl_xor_sync(0xffffffffu, sa, 1);
    ssb += __shfl_xor_sync(0xffffffffu, ssb, 1);
    sB  += __shfl_xor_sync(0xffffffffu, sB, 1);
    __syncthreads();   // all frag reads done before smem reuse of r1/r2 region write order
    if (h == 0) {
        smf[R1_OFF + row] = ssa + 2.0f * EPSV * sa;
        smf[R2_OFF + row] = ssb - 2.0f * EPSV * sB + (float)DDIM * EPSV * EPSV;
    }
    __syncthreads();

    // ---- epilogue: d = sqrt(max(r1 + r2 - 2*dot, 0)), direct float2 stores ----
    float r1v[4][2];
#pragma unroll
    for (int mt = 0; mt < 4; mt++) {
        r1v[mt][0] = smf[R1_OFF + wm * 64 + mt * 16 + g];
        r1v[mt][1] = smf[R1_OFF + wm * 64 + mt * 16 + g + 8];
    }
    float2 r2v[4];
#pragma unroll
    for (int nt = 0; nt < 4; nt++)
        r2v[nt] = *reinterpret_cast<const float2*>(&smf[R2_OFF + wn * 32 + nt * 8 + klane]);

    float* Ob = out + ((size_t)(b * LDIM + m0)) * LDIM + n0;
#pragma unroll
    for (int mt = 0; mt < 4; mt++) {
#pragma unroll
        for (int nt = 0; nt < 4; nt++) {
            const int col  = wn * 32 + nt * 8 + klane;
            const int row0 = wm * 64 + mt * 16 + g;
            float2 v0, v1;
            v0.x = fsqrt_fast(fmaxf(r1v[mt][0] + r2v[nt].x - 2.0f * acc[mt][nt][0], 0.f));
            v0.y = fsqrt_fast(fmaxf(r1v[mt][0] + r2v[nt].y - 2.0f * acc[mt][nt][1], 0.f));
            v1.x = fsqrt_fast(fmaxf(r1v[mt][1] + r2v[nt].x - 2.0f * acc[mt][nt][2], 0.f));
            v1.y = fsqrt_fast(fmaxf(r1v[mt][1] + r2v[nt].y - 2.0f * acc[mt][nt][3], 0.f));
            *reinterpret_cast<float2*>(Ob + (size_t)row0 * LDIM + col)       = v0;
            *reinterpret_cast<float2*>(Ob + (size_t)(row0 + 8) * LDIM + col) = v1;
        }
    }
}

// ---------------------------------------------------------------------------
extern "C" void kernel_launch(void* const* d_in, const int* in_sizes, int n_in,
                              void* d_out, int out_size) {
    const float* A = (const float*)d_in[0];
    const float* B = (const float*)d_in[1];
    float* out = (float*)d_out;
    (void)in_sizes; (void)n_in; (void)out_size;

    cudaFuncSetAttribute(dist_tf32_kernel,
                         cudaFuncAttributeMaxDynamicSharedMemorySize, SMEM_BYTES);
    dim3 grid(LDIM / TN, LDIM / TM, BATCH);
    dist_tf32_kernel<<<grid, 256, SMEM_BYTES>>>(A, B, out);
}